// round 11
// baseline (speedup 1.0000x reference)
#include <cuda_runtime.h>
#include <cstdint>

#define VOCAB 50257
#define EMBED 128
#define BATCH 64
#define NSENT 50
#define TC 20
#define TQ 20
#define NHOPS 3

// Scratch (device global — no allocation allowed)
__device__ float g_u[BATCH * EMBED];
__device__ float g_m[BATCH * NSENT * EMBED];
__device__ float g_c[BATCH * NSENT * EMBED];

// ---------------------------------------------------------------------------
// Kernel 1: embedding sums. TWO warps per sentence (m-warp / c-warp).
// ---------------------------------------------------------------------------
__global__ void __launch_bounds__(128) embed_kernel(
        const int* __restrict__ stories,
        const int* __restrict__ questions,
        const int* __restrict__ masks,
        const float* __restrict__ WA,
        const float* __restrict__ WB,
        const float* __restrict__ WC,
        const float* __restrict__ WAT,
        const float* __restrict__ WCT) {
    int gwarp = (blockIdx.x * blockDim.x + threadIdx.x) >> 5;
    int lane = threadIdx.x & 31;

    if (gwarp < 2 * BATCH * NSENT) {
        int sent = gwarp >> 1;
        int half = gwarp & 1;
        int s = sent % NSENT;
        int mytok = (lane < TC) ? stories[sent * TC + lane] : 0;
        int mymsk = (lane < TC) ? masks[sent * TC + lane] : 1;
        unsigned ball = __ballot_sync(0xffffffffu, (lane < TC) && (mymsk == 0));
        int te = (ball != 0u) ? (s + 1) : 0;

        const float* tbl = half ? WC : WA;
        const float* ttbl = half ? WCT : WAT;
        float4 acc = *(const float4*)&ttbl[te * EMBED + lane * 4];
#pragma unroll
        for (int t = 0; t < TC; t++) {
            int tk = __shfl_sync(0xffffffffu, mytok, t);
            float4 a = *(const float4*)&tbl[(size_t)tk * EMBED + lane * 4];
            acc.x += a.x; acc.y += a.y; acc.z += a.z; acc.w += a.w;
        }
        float* dst = half ? g_c : g_m;
        *(float4*)&dst[(size_t)sent * EMBED + lane * 4] = acc;
    } else if (gwarp < 2 * BATCH * NSENT + BATCH) {
        int b = gwarp - 2 * BATCH * NSENT;
        int myq = (lane < TQ) ? questions[b * TQ + lane] : 0;
        float4 u = make_float4(0.f, 0.f, 0.f, 0.f);
#pragma unroll
        for (int t = 0; t < TQ; t++) {
            int tk = __shfl_sync(0xffffffffu, myq, t);
            float4 a = *(const float4*)&WB[(size_t)tk * EMBED + lane * 4];
            u.x += a.x; u.y += a.y; u.z += a.z; u.w += a.w;
        }
        *(float4*)&g_u[b * EMBED + lane * 4] = u;
    }
}

// ---------------------------------------------------------------------------
// Kernel 2: hops with full smem residency. One block per batch, 256 threads.
// ---------------------------------------------------------------------------
#define HOPS_SMEM ((2 * NSENT * EMBED + EMBED + 64) * 4)

__global__ void __launch_bounds__(256) hops_kernel() {
    extern __shared__ float hs[];
    float* m_s = hs;
    float* c_s = hs + NSENT * EMBED;
    float* u_s = hs + 2 * NSENT * EMBED;
    float* sc = u_s + EMBED;

    int b = blockIdx.x;
    int tid = threadIdx.x;
    int w = tid >> 5, lane = tid & 31;

    const float4* gm = (const float4*)&g_m[(size_t)b * NSENT * EMBED];
    const float4* gc = (const float4*)&g_c[(size_t)b * NSENT * EMBED];
#pragma unroll
    for (int i = 0; i < 7; i++) {
        int q = tid + 256 * i;
        if (q < NSENT * EMBED / 4) {
            ((float4*)m_s)[q] = gm[q];
            ((float4*)c_s)[q] = gc[q];
        }
    }
    if (tid < EMBED) u_s[tid] = g_u[b * EMBED + tid];
    __syncthreads();

    for (int hop = 0; hop < NHOPS; hop++) {
        float4 uv = *(const float4*)&u_s[lane * 4];
        for (int n = w; n < NSENT; n += 8) {
            float4 mv = *(const float4*)&m_s[n * EMBED + lane * 4];
            float p = mv.x * uv.x + mv.y * uv.y + mv.z * uv.z + mv.w * uv.w;
#pragma unroll
            for (int o = 16; o > 0; o >>= 1) p += __shfl_xor_sync(0xffffffffu, p, o);
            if (lane == 0) sc[n] = p;
        }
        __syncthreads();
        if (w == 0) {
            float v0 = (lane < NSENT) ? sc[lane] : -1e30f;
            float v1 = (lane + 32 < NSENT) ? sc[lane + 32] : -1e30f;
            float mx = fmaxf(v0, v1);
#pragma unroll
            for (int o = 16; o > 0; o >>= 1) mx = fmaxf(mx, __shfl_xor_sync(0xffffffffu, mx, o));
            float e0 = (lane < NSENT) ? expf(v0 - mx) : 0.f;
            float e1 = (lane + 32 < NSENT) ? expf(v1 - mx) : 0.f;
            float s = e0 + e1;
#pragma unroll
            for (int o = 16; o > 0; o >>= 1) s += __shfl_xor_sync(0xffffffffu, s, o);
            float inv = 1.f / s;
            if (lane < NSENT) sc[lane] = e0 * inv;
            if (lane + 32 < NSENT) sc[lane + 32] = e1 * inv;
        }
        __syncthreads();
        if (tid < EMBED) {
            float o_acc = 0.f;
#pragma unroll 10
            for (int n = 0; n < NSENT; n++)
                o_acc += c_s[n * EMBED + tid] * sc[n];
            u_s[tid] += o_acc;
        }
        __syncthreads();
    }
    if (tid < EMBED) g_u[b * EMBED + tid] = u_s[tid];
}

// ---------------------------------------------------------------------------
// Kernel 3: logits via tf32 mma.sync, persistent CTAs + cp.async double buffer.
// 64-row tiles so smem = 101.4KB -> 2 CTAs/SM (16 warps/SM, cross-CTA overlap).
// Grid 296; CTA handles tiles bid, bid+296, bid+592 of 786.
// Warp (rw = wid&3, bh = wid>>2): rows rw*16 + {gid, gid+8}, batches bh*32+...
// ---------------------------------------------------------------------------
__device__ __forceinline__ uint32_t tf32b(float x) {
    float r;
    asm("cvt.rna.tf32.f32 %0, %1;" : "=f"(r) : "f"(x));
    return __float_as_uint(r);
}
__device__ __forceinline__ void mma_tf32(float* c, const uint32_t* a,
                                         uint32_t b0, uint32_t b1) {
    asm volatile(
        "mma.sync.aligned.m16n8k8.row.col.f32.tf32.tf32.f32 "
        "{%0,%1,%2,%3}, {%4,%5,%6,%7}, {%8,%9}, {%0,%1,%2,%3};"
        : "+f"(c[0]), "+f"(c[1]), "+f"(c[2]), "+f"(c[3])
        : "r"(a[0]), "r"(a[1]), "r"(a[2]), "r"(a[3]), "r"(b0), "r"(b1));
}
__device__ __forceinline__ uint32_t sm_u32(const void* p) {
    uint32_t a;
    asm("{ .reg .u64 t; cvta.to.shared.u64 t, %1; cvt.u32.u64 %0, t; }"
        : "=r"(a) : "l"(p));
    return a;
}
__device__ __forceinline__ void cp_async16(uint32_t dst, const void* src) {
    asm volatile("cp.async.ca.shared.global [%0], [%1], 16;"
                 :: "r"(dst), "l"(src) : "memory");
}

#define LPAD 132
#define TROWS 64
#define NTILES 786          // ceil(VOCAB/64)
#define LG_GRID 296
#define LG_SMEM_BYTES ((64 + 2 * TROWS) * LPAD * 4)   // 101376

__global__ void __launch_bounds__(256) logits_mma_kernel(
        const float* __restrict__ W,
        const float* __restrict__ bias,
        float* __restrict__ out) {
    extern __shared__ uint32_t sh[];
    uint32_t (*us)[LPAD] = (uint32_t(*)[LPAD])sh;          // 64 rows tf32 (u)
    float* wbuf[2];
    wbuf[0] = (float*)(sh + 64 * LPAD);                    // 64 rows fp32 (W)
    wbuf[1] = (float*)(sh + (64 + TROWS) * LPAD);

    int tid = threadIdx.x;
    int wid = tid >> 5, lane = tid & 31;
    int gid = lane >> 2, tig = lane & 3;
    int rw = wid & 3;       // row group
    int bh = wid >> 2;      // batch half
    int bid = blockIdx.x;

    // ---- stage u -> tf32 smem (64 x 128) ----
#pragma unroll
    for (int i = 0; i < 8; i++) {
        int q = tid + 256 * i;
        int row = q >> 5, kq = q & 31;
        float4 v = *(const float4*)(g_u + row * EMBED + kq * 4);
        us[row][kq * 4 + 0] = tf32b(v.x);
        us[row][kq * 4 + 1] = tf32b(v.y);
        us[row][kq * 4 + 2] = tf32b(v.z);
        us[row][kq * 4 + 3] = tf32b(v.w);
    }

    auto prefetch = [&](int j) {
        int tile = bid + LG_GRID * j;
        if (tile < NTILES) {
            int row0 = tile * TROWS;
            uint32_t base = sm_u32(wbuf[j & 1]);
#pragma unroll
            for (int i = 0; i < 8; i++) {           // 64 rows * 32 quads / 256
                int q = tid + 256 * i;
                int row = q >> 5, kq = q & 31;
                int grow = row0 + row;
                if (grow > VOCAB - 1) grow = VOCAB - 1;
                cp_async16(base + (uint32_t)(row * LPAD + kq * 4) * 4,
                           W + (size_t)grow * EMBED + kq * 4);
            }
        }
        asm volatile("cp.async.commit_group;" ::: "memory");
    };

    prefetch(0);
    prefetch(1);

    int rl = rw * 16 + gid;
    int rh = rl + 8;

    for (int j = 0; j < 3; j++) {
        int tile = bid + LG_GRID * j;
        if (tile >= NTILES) break;
        asm volatile("cp.async.wait_group 1;" ::: "memory");
        __syncthreads();

        const float* ws = wbuf[j & 1];
        float acc[4][4];
#pragma unroll
        for (int jj = 0; jj < 4; jj++)
#pragma unroll
            for (int q = 0; q < 4; q++) acc[jj][q] = 0.f;

#pragma unroll
        for (int s = 0; s < 16; s++) {
            int k0 = s * 8 + tig;
            uint32_t a[4];
            a[0] = tf32b(ws[rl * LPAD + k0]);
            a[1] = tf32b(ws[rh * LPAD + k0]);
            a[2] = tf32b(ws[rl * LPAD + k0 + 4]);
            a[3] = tf32b(ws[rh * LPAD + k0 + 4]);
#pragma unroll
            for (int jj = 0; jj < 4; jj++) {
                int un = bh * 32 + jj * 8 + gid;
                uint32_t b0 = us[un][k0];
                uint32_t b1 = us[un][k0 + 4];
                mma_tf32(acc[jj], a, b0, b1);
            }
        }

        // epilogue for this tile
        int row0 = tile * TROWS;
        int r_lo = row0 + rl;
        int r_hi = row0 + rh;
        bool vlo = (r_lo < VOCAB), vhi = (r_hi < VOCAB);
        float blo = vlo ? __ldg(bias + r_lo) : 0.f;
        float bhi = vhi ? __ldg(bias + r_hi) : 0.f;
#pragma unroll
        for (int jj = 0; jj < 4; jj++) {
            int n0 = bh * 32 + jj * 8 + 2 * tig;
            int n1 = n0 + 1;
            if (vlo) {
                out[(size_t)n0 * VOCAB + r_lo] = acc[jj][0] + blo;
                out[(size_t)n1 * VOCAB + r_lo] = acc[jj][1] + blo;
            }
            if (vhi) {
                out[(size_t)n0 * VOCAB + r_hi] = acc[jj][2] + bhi;
                out[(size_t)n1 * VOCAB + r_hi] = acc[jj][3] + bhi;
            }
        }

        __syncthreads();
        prefetch(j + 2);
    }
}

extern "C" void kernel_launch(void* const* d_in, const int* in_sizes, int n_in,
                              void* d_out, int out_size) {
    const int* stories = (const int*)d_in[0];
    const int* questions = (const int*)d_in[1];
    const int* masks = (const int*)d_in[2];
    const float* WA = (const float*)d_in[3];
    const float* WB = (const float*)d_in[4];
    const float* WC = (const float*)d_in[5];
    const float* WAT = (const float*)d_in[6];
    const float* WCT = (const float*)d_in[7];
    const float* Wlin = (const float*)d_in[8];
    const float* blin = (const float*)d_in[9];
    float* out = (float*)d_out;

    int total_warps = 2 * BATCH * NSENT + BATCH;
    int embed_blocks = (total_warps * 32 + 127) / 128;
    embed_kernel<<<embed_blocks, 128>>>(stories, questions, masks, WA, WB, WC, WAT, WCT);

    cudaFuncSetAttribute(hops_kernel, cudaFuncAttributeMaxDynamicSharedMemorySize,
                         HOPS_SMEM);
    hops_kernel<<<BATCH, 256, HOPS_SMEM>>>();

    cudaFuncSetAttribute(logits_mma_kernel,
                         cudaFuncAttributeMaxDynamicSharedMemorySize, LG_SMEM_BYTES);
    logits_mma_kernel<<<LG_GRID, 256, LG_SMEM_BYTES>>>(Wlin, blin, out);
}

// round 14
// speedup vs baseline: 1.0072x; 1.0072x over previous
#include <cuda_runtime.h>
#include <cstdint>

#define VOCAB 50257
#define EMBED 128
#define BATCH 64
#define NSENT 50
#define TC 20
#define TQ 20
#define NHOPS 3

// Scratch (device global — no allocation allowed)
__device__ float g_u[BATCH * EMBED];
__device__ float g_m[BATCH * NSENT * EMBED];
__device__ float g_c[BATCH * NSENT * EMBED];

// ---------------------------------------------------------------------------
// Kernel 1: embedding sums. TWO warps per sentence (m-warp / c-warp), plus
// 160 trailing blocks that prefetch the whole W_lin into L2 (warm for logits).
// ---------------------------------------------------------------------------
#define EMB_WARPS (2 * BATCH * NSENT + BATCH)          // 6464
#define PF_BLOCKS 160
#define W_LINES (VOCAB * 4)                            // 128B lines in W_lin

__global__ void __launch_bounds__(128) embed_kernel(
        const int* __restrict__ stories,
        const int* __restrict__ questions,
        const int* __restrict__ masks,
        const float* __restrict__ WA,
        const float* __restrict__ WB,
        const float* __restrict__ WC,
        const float* __restrict__ WAT,
        const float* __restrict__ WCT,
        const float* __restrict__ Wlin) {
    int gwarp = (blockIdx.x * blockDim.x + threadIdx.x) >> 5;
    int lane = threadIdx.x & 31;

    if (gwarp < 2 * BATCH * NSENT) {
        int sent = gwarp >> 1;
        int half = gwarp & 1;
        int s = sent % NSENT;
        int mytok = (lane < TC) ? stories[sent * TC + lane] : 0;
        int mymsk = (lane < TC) ? masks[sent * TC + lane] : 1;
        unsigned ball = __ballot_sync(0xffffffffu, (lane < TC) && (mymsk == 0));
        int te = (ball != 0u) ? (s + 1) : 0;

        const float* tbl = half ? WC : WA;
        const float* ttbl = half ? WCT : WAT;
        float4 acc = *(const float4*)&ttbl[te * EMBED + lane * 4];
#pragma unroll
        for (int t = 0; t < TC; t++) {
            int tk = __shfl_sync(0xffffffffu, mytok, t);
            float4 a = *(const float4*)&tbl[(size_t)tk * EMBED + lane * 4];
            acc.x += a.x; acc.y += a.y; acc.z += a.z; acc.w += a.w;
        }
        float* dst = half ? g_c : g_m;
        *(float4*)&dst[(size_t)sent * EMBED + lane * 4] = acc;
    } else if (gwarp < EMB_WARPS) {
        int b = gwarp - 2 * BATCH * NSENT;
        int myq = (lane < TQ) ? questions[b * TQ + lane] : 0;
        float4 u = make_float4(0.f, 0.f, 0.f, 0.f);
#pragma unroll
        for (int t = 0; t < TQ; t++) {
            int tk = __shfl_sync(0xffffffffu, myq, t);
            float4 a = *(const float4*)&WB[(size_t)tk * EMBED + lane * 4];
            u.x += a.x; u.y += a.y; u.z += a.z; u.w += a.w;
        }
        *(float4*)&g_u[b * EMBED + lane * 4] = u;
    } else {
        // prefetch warps: warm L2 with the logits weight matrix
        int p = gwarp - EMB_WARPS;                 // 0 .. PF_BLOCKS*4-1
        int nthr = PF_BLOCKS * 128;                // prefetch threads
        int t0 = p * 32 + lane;
#pragma unroll 4
        for (int idx = t0; idx < W_LINES; idx += nthr) {
            const float* ptr = Wlin + (size_t)idx * 32;   // 128B line
            asm volatile("prefetch.global.L2 [%0];" :: "l"(ptr));
        }
    }
}

// ---------------------------------------------------------------------------
// Kernel 2: hops with full smem residency. One block per batch, 256 threads.
// ---------------------------------------------------------------------------
#define HOPS_SMEM ((2 * NSENT * EMBED + EMBED + 64) * 4)

__global__ void __launch_bounds__(256) hops_kernel() {
    extern __shared__ float hs[];
    float* m_s = hs;
    float* c_s = hs + NSENT * EMBED;
    float* u_s = hs + 2 * NSENT * EMBED;
    float* sc = u_s + EMBED;

    int b = blockIdx.x;
    int tid = threadIdx.x;
    int w = tid >> 5, lane = tid & 31;

    const float4* gm = (const float4*)&g_m[(size_t)b * NSENT * EMBED];
    const float4* gc = (const float4*)&g_c[(size_t)b * NSENT * EMBED];
#pragma unroll
    for (int i = 0; i < 7; i++) {
        int q = tid + 256 * i;
        if (q < NSENT * EMBED / 4) {
            ((float4*)m_s)[q] = gm[q];
            ((float4*)c_s)[q] = gc[q];
        }
    }
    if (tid < EMBED) u_s[tid] = g_u[b * EMBED + tid];
    __syncthreads();

    for (int hop = 0; hop < NHOPS; hop++) {
        float4 uv = *(const float4*)&u_s[lane * 4];
        for (int n = w; n < NSENT; n += 8) {
            float4 mv = *(const float4*)&m_s[n * EMBED + lane * 4];
            float p = mv.x * uv.x + mv.y * uv.y + mv.z * uv.z + mv.w * uv.w;
#pragma unroll
            for (int o = 16; o > 0; o >>= 1) p += __shfl_xor_sync(0xffffffffu, p, o);
            if (lane == 0) sc[n] = p;
        }
        __syncthreads();
        if (w == 0) {
            float v0 = (lane < NSENT) ? sc[lane] : -1e30f;
            float v1 = (lane + 32 < NSENT) ? sc[lane + 32] : -1e30f;
            float mx = fmaxf(v0, v1);
#pragma unroll
            for (int o = 16; o > 0; o >>= 1) mx = fmaxf(mx, __shfl_xor_sync(0xffffffffu, mx, o));
            float e0 = (lane < NSENT) ? expf(v0 - mx) : 0.f;
            float e1 = (lane + 32 < NSENT) ? expf(v1 - mx) : 0.f;
            float s = e0 + e1;
#pragma unroll
            for (int o = 16; o > 0; o >>= 1) s += __shfl_xor_sync(0xffffffffu, s, o);
            float inv = 1.f / s;
            if (lane < NSENT) sc[lane] = e0 * inv;
            if (lane + 32 < NSENT) sc[lane + 32] = e1 * inv;
        }
        __syncthreads();
        if (tid < EMBED) {
            float o_acc = 0.f;
#pragma unroll 10
            for (int n = 0; n < NSENT; n++)
                o_acc += c_s[n * EMBED + tid] * sc[n];
            u_s[tid] += o_acc;
        }
        __syncthreads();
    }
    if (tid < EMBED) g_u[b * EMBED + tid] = u_s[tid];
}

// ---------------------------------------------------------------------------
// Kernel 3: logits via tf32 mma.sync, persistent CTAs + cp.async double buffer
// (R10 config; W now L2-hot from the embed prefetch warps).
// ---------------------------------------------------------------------------
__device__ __forceinline__ uint32_t tf32b(float x) {
    float r;
    asm("cvt.rna.tf32.f32 %0, %1;" : "=f"(r) : "f"(x));
    return __float_as_uint(r);
}
__device__ __forceinline__ void mma_tf32(float* c, const uint32_t* a,
                                         uint32_t b0, uint32_t b1) {
    asm volatile(
        "mma.sync.aligned.m16n8k8.row.col.f32.tf32.tf32.f32 "
        "{%0,%1,%2,%3}, {%4,%5,%6,%7}, {%8,%9}, {%0,%1,%2,%3};"
        : "+f"(c[0]), "+f"(c[1]), "+f"(c[2]), "+f"(c[3])
        : "r"(a[0]), "r"(a[1]), "r"(a[2]), "r"(a[3]), "r"(b0), "r"(b1));
}
__device__ __forceinline__ uint32_t sm_u32(const void* p) {
    uint32_t a;
    asm("{ .reg .u64 t; cvta.to.shared.u64 t, %1; cvt.u32.u64 %0, t; }"
        : "=r"(a) : "l"(p));
    return a;
}
__device__ __forceinline__ void cp_async16(uint32_t dst, const void* src) {
    asm volatile("cp.async.ca.shared.global [%0], [%1], 16;"
                 :: "r"(dst), "l"(src) : "memory");
}

#define LPAD 132
#define NTILES 393
#define LG_GRID 148
#define LG_SMEM_BYTES ((64 + 2 * 128) * LPAD * 4)

__global__ void __launch_bounds__(256) logits_mma_kernel(
        const float* __restrict__ W,
        const float* __restrict__ bias,
        float* __restrict__ out) {
    extern __shared__ uint32_t sh[];
    uint32_t (*us)[LPAD] = (uint32_t(*)[LPAD])sh;                 // 64 rows tf32
    float* wbuf[2];
    wbuf[0] = (float*)(sh + 64 * LPAD);                           // 128 rows fp32
    wbuf[1] = (float*)(sh + (64 + 128) * LPAD);

    int tid = threadIdx.x;
    int wid = tid >> 5, lane = tid & 31;
    int gid = lane >> 2, tig = lane & 3;
    int bid = blockIdx.x;

    // ---- stage u -> tf32 smem (64 x 128) ----
#pragma unroll
    for (int i = 0; i < 8; i++) {
        int q = tid + 256 * i;
        int row = q >> 5, kq = q & 31;
        float4 v = *(const float4*)(g_u + row * EMBED + kq * 4);
        us[row][kq * 4 + 0] = tf32b(v.x);
        us[row][kq * 4 + 1] = tf32b(v.y);
        us[row][kq * 4 + 2] = tf32b(v.z);
        us[row][kq * 4 + 3] = tf32b(v.w);
    }

    auto prefetch = [&](int j) {
        int tile = bid + LG_GRID * j;
        if (tile < NTILES) {
            int row0 = tile * 128;
            uint32_t base = sm_u32(wbuf[j & 1]);
#pragma unroll
            for (int i = 0; i < 16; i++) {
                int q = tid + 256 * i;
                int row = q >> 5, kq = q & 31;
                int grow = row0 + row;
                if (grow > VOCAB - 1) grow = VOCAB - 1;
                cp_async16(base + (uint32_t)(row * LPAD + kq * 4) * 4,
                           W + (size_t)grow * EMBED + kq * 4);
            }
        }
        asm volatile("cp.async.commit_group;" ::: "memory");
    };

    prefetch(0);
    prefetch(1);

    int rl = wid * 16 + gid;
    int rh = rl + 8;

    for (int j = 0; j < 3; j++) {
        int tile = bid + LG_GRID * j;
        if (tile >= NTILES) break;
        asm volatile("cp.async.wait_group 1;" ::: "memory");
        __syncthreads();

        const float* ws = wbuf[j & 1];
        float acc[8][4];
#pragma unroll
        for (int jj = 0; jj < 8; jj++)
#pragma unroll
            for (int q = 0; q < 4; q++) acc[jj][q] = 0.f;

#pragma unroll
        for (int s = 0; s < 16; s++) {
            int k0 = s * 8 + tig;
            uint32_t a[4];
            a[0] = tf32b(ws[rl * LPAD + k0]);
            a[1] = tf32b(ws[rh * LPAD + k0]);
            a[2] = tf32b(ws[rl * LPAD + k0 + 4]);
            a[3] = tf32b(ws[rh * LPAD + k0 + 4]);
#pragma unroll
            for (int jj = 0; jj < 8; jj++) {
                uint32_t b0 = us[jj * 8 + gid][k0];
                uint32_t b1 = us[jj * 8 + gid][k0 + 4];
                mma_tf32(acc[jj], a, b0, b1);
            }
        }

        int row0 = tile * 128;
        int r_lo = row0 + rl;
        int r_hi = row0 + rh;
        bool vlo = (r_lo < VOCAB), vhi = (r_hi < VOCAB);
        float blo = vlo ? __ldg(bias + r_lo) : 0.f;
        float bhi = vhi ? __ldg(bias + r_hi) : 0.f;
#pragma unroll
        for (int jj = 0; jj < 8; jj++) {
            int n0 = jj * 8 + 2 * tig;
            int n1 = n0 + 1;
            if (vlo) {
                out[(size_t)n0 * VOCAB + r_lo] = acc[jj][0] + blo;
                out[(size_t)n1 * VOCAB + r_lo] = acc[jj][1] + blo;
            }
            if (vhi) {
                out[(size_t)n0 * VOCAB + r_hi] = acc[jj][2] + bhi;
                out[(size_t)n1 * VOCAB + r_hi] = acc[jj][3] + bhi;
            }
        }

        __syncthreads();
        prefetch(j + 2);
    }
}

extern "C" void kernel_launch(void* const* d_in, const int* in_sizes, int n_in,
                              void* d_out, int out_size) {
    const int* stories = (const int*)d_in[0];
    const int* questions = (const int*)d_in[1];
    const int* masks = (const int*)d_in[2];
    const float* WA = (const float*)d_in[3];
    const float* WB = (const float*)d_in[4];
    const float* WC = (const float*)d_in[5];
    const float* WAT = (const float*)d_in[6];
    const float* WCT = (const float*)d_in[7];
    const float* Wlin = (const float*)d_in[8];
    const float* blin = (const float*)d_in[9];
    float* out = (float*)d_out;

    int embed_blocks = (EMB_WARPS * 32 + 127) / 128 + PF_BLOCKS;
    embed_kernel<<<embed_blocks, 128>>>(stories, questions, masks,
                                        WA, WB, WC, WAT, WCT, Wlin);

    cudaFuncSetAttribute(hops_kernel, cudaFuncAttributeMaxDynamicSharedMemorySize,
                         HOPS_SMEM);
    hops_kernel<<<BATCH, 256, HOPS_SMEM>>>();

    cudaFuncSetAttribute(logits_mma_kernel,
                         cudaFuncAttributeMaxDynamicSharedMemorySize, LG_SMEM_BYTES);
    logits_mma_kernel<<<LG_GRID, 256, LG_SMEM_BYTES>>>(Wlin, blin, out);
}